// round 3
// baseline (speedup 1.0000x reference)
#include <cuda_runtime.h>
#include <math.h>

#define BB 2
#define SS 2048
#define NCOND 2
#define STOK 2046
#define DD 512
#define HH 8
#define DHD 64
#define DI 2048
#define NL 6
#define VV 512
#define BS (BB*SS)   // 4096

// ---------------- scratch (device globals; no allocations allowed) ----------
__device__ float g_x[BS*DD];
__device__ float g_q[BS*DD];
__device__ float g_k[BS*DD];
__device__ float g_v[BS*DD];
__device__ float g_attn[BS*DD];
__device__ float g_res[BS*DD];
__device__ float g_out1[BS*DD];
__device__ float g_h[BS*DI];
__device__ float g_chordf[BS];
__device__ int   g_keypad[BS];

// ---------------- misc: keypad + chord factor --------------------------------
__global__ void k_misc(const int* __restrict__ toks, const float* __restrict__ ttc) {
    int idx = blockIdx.x * 256 + threadIdx.x;
    if (idx >= BS) return;
    int b = idx / SS, s = idx % SS;
    g_keypad[idx] = (s >= NCOND && toks[b*STOK + s - NCOND] == 0) ? 1 : 0;
    float t = (s < NCOND) ? ttc[b*STOK] : ttc[b*STOK + s - NCOND];
    g_chordf[idx] = 8.0f - t;
}

// ---------------- build x: cond MLP / embedding + pos ------------------------
__global__ void k_build_x(const int* __restrict__ toks, const float* __restrict__ cond,
                          const float* __restrict__ emb, const float* __restrict__ pos,
                          const float* __restrict__ W1, const float* __restrict__ b1,
                          const float* __restrict__ W2, const float* __restrict__ b2,
                          const float* __restrict__ nullc) {
    int blk = blockIdx.x;            // = b*SS + s
    int b = blk / SS, s = blk % SS;
    int t = threadIdx.x;             // 128 threads
    if (s < NCOND) {
        __shared__ float h1[256];
        float c = cond[b*NCOND + s];
        bool isn = isnan(c);
        if (!isn) {
            for (int o = t; o < 256; o += 128)
                h1[o] = fmaxf(c * W1[s*256 + o] + b1[s*256 + o], 0.f);
        }
        __syncthreads();
        for (int d = t; d < DD; d += 128) {
            float ce;
            if (isn) ce = nullc[s*DD + d];
            else {
                float acc = b2[s*DD + d];
                #pragma unroll 8
                for (int o = 0; o < 256; o++) acc += h1[o] * W2[(s*256 + o)*DD + d];
                ce = acc;
            }
            g_x[blk*DD + d] = ce + pos[s*DD + d];
        }
    } else {
        int tok = toks[b*STOK + s - NCOND];
        const float* e = emb + tok*DD;
        for (int d = t; d < DD; d += 128)
            g_x[blk*DD + d] = e[d] * 22.62741699796952f + pos[s*DD + d];
    }
}

// ---------------- generic 64x64 SGEMM with fused epilogues --------------------
// MODE 0: QKV permute store  out[((b*H+h)*S+s)*DH + d] = acc+bias
// MODE 1: out = acc + bias + res
// MODE 2: out = relu(acc+bias) + chordf[r]*ttcW[c] + ttcb[c]
// MODE 3: out = acc + bias
template<int MODE>
__global__ void gemm64(const float* __restrict__ A, const float* __restrict__ W,
                       const float* __restrict__ bias, const float* __restrict__ res,
                       float* __restrict__ out, int M, int N, int K,
                       const float* __restrict__ ttcW, const float* __restrict__ ttcb) {
    __shared__ float As[16][68];
    __shared__ float Ws[16][68];
    int t  = threadIdx.x;
    int tx = t & 15, ty = t >> 4;
    int m0 = blockIdx.y * 64, n0 = blockIdx.x * 64;
    float acc[4][4] = {};
    for (int k0 = 0; k0 < K; k0 += 16) {
        {
            int mr = t >> 2, kc = (t & 3) * 4;
            float4 av = *(const float4*)(A + (size_t)(m0 + mr)*K + k0 + kc);
            As[kc+0][mr] = av.x; As[kc+1][mr] = av.y;
            As[kc+2][mr] = av.z; As[kc+3][mr] = av.w;
            int kr = t >> 4, nc = (t & 15) * 4;
            *(float4*)(&Ws[kr][nc]) = *(const float4*)(W + (size_t)(k0 + kr)*N + n0 + nc);
        }
        __syncthreads();
        #pragma unroll
        for (int kk = 0; kk < 16; kk++) {
            float4 a = *(const float4*)(&As[kk][ty*4]);
            float4 w = *(const float4*)(&Ws[kk][tx*4]);
            float ar[4] = {a.x, a.y, a.z, a.w};
            float wr[4] = {w.x, w.y, w.z, w.w};
            #pragma unroll
            for (int ii = 0; ii < 4; ii++)
                #pragma unroll
                for (int jj = 0; jj < 4; jj++)
                    acc[ii][jj] += ar[ii] * wr[jj];
        }
        __syncthreads();
    }
    #pragma unroll
    for (int ii = 0; ii < 4; ii++) {
        int r = m0 + ty*4 + ii;
        #pragma unroll
        for (int jj = 0; jj < 4; jj++) {
            int c = n0 + tx*4 + jj;
            float v = acc[ii][jj] + bias[c];
            if (MODE == 0) {
                int b = r >> 11, s = r & 2047, h = c >> 6, d = c & 63;
                out[(((size_t)(b*HH + h))*SS + s)*DHD + d] = v;
            } else if (MODE == 1) {
                out[(size_t)r*N + c] = v + res[(size_t)r*N + c];
            } else if (MODE == 2) {
                out[(size_t)r*N + c] = fmaxf(v, 0.f) + g_chordf[r]*ttcW[c] + ttcb[c];
            } else {
                out[(size_t)r*N + c] = v;
            }
        }
    }
}

// ---------------- layernorm (one block per row of 512) ------------------------
__global__ void k_ln(const float* __restrict__ in, float* __restrict__ out,
                     const float* __restrict__ g, const float* __restrict__ bb) {
    int r = blockIdx.x, t = threadIdx.x;    // 128 threads
    float4 v = *(const float4*)(in + (size_t)r*DD + t*4);
    float s  = v.x + v.y + v.z + v.w;
    float ss = v.x*v.x + v.y*v.y + v.z*v.z + v.w*v.w;
    for (int m = 16; m; m >>= 1) {
        s  += __shfl_xor_sync(0xffffffffu, s,  m);
        ss += __shfl_xor_sync(0xffffffffu, ss, m);
    }
    __shared__ float sm[4], sm2[4];
    if ((t & 31) == 0) { sm[t>>5] = s; sm2[t>>5] = ss; }
    __syncthreads();
    s  = sm[0]  + sm[1]  + sm[2]  + sm[3];
    ss = sm2[0] + sm2[1] + sm2[2] + sm2[3];
    float mu  = s * (1.0f/DD);
    float var = ss * (1.0f/DD) - mu*mu;
    float inv = rsqrtf(var + 1e-6f);
    float4 gg = *(const float4*)(g  + t*4);
    float4 bv = *(const float4*)(bb + t*4);
    float4 o;
    o.x = (v.x - mu)*inv*gg.x + bv.x;
    o.y = (v.y - mu)*inv*gg.y + bv.y;
    o.z = (v.z - mu)*inv*gg.z + bv.z;
    o.w = (v.w - mu)*inv*gg.w + bv.w;
    *(float4*)(out + (size_t)r*DD + t*4) = o;
}

// ---------------- fused relative-position flash attention ---------------------
// grid: (S/64, H, B), 256 threads, dynamic smem 86272 B.
// Srel[i,j] (j<=i) = q_i . E[S-1+j-i]  -> in-tile Z[i,u]=q_i.E[base+u], u=jj-ii+63
#define ATT_SMEM (86272)
__global__ __launch_bounds__(256, 1)
void k_attn(const float* __restrict__ E) {
    extern __shared__ float smem[];
    float* QT = smem;                 // [64][68] q^T  : QT[d][i]
    float* KT = QT + 64*68;           // [64][68] k^T  : KT[d][j]   (alias: P^T[j][i])
    float* VS = KT + 64*68;           // [64][68] v    : VS[j][d]
    float* ET = VS + 64*68;           // [64][132] e^T : ET[d][u]   (alias: Z[i][u])
    int*   KP = (int*)(ET + 64*132);  // [64]

    int t  = threadIdx.x;
    int tx = t & 15, ty = t >> 4;
    int i0 = blockIdx.x * 64, h = blockIdx.y, b = blockIdx.z;
    const float* qg = g_q + ((size_t)(b*HH + h))*SS*DHD;
    const float* kg = g_k + ((size_t)(b*HH + h))*SS*DHD;
    const float* vg = g_v + ((size_t)(b*HH + h))*SS*DHD;

    #pragma unroll
    for (int c = 0; c < 4; c++) {
        int vid = t + 256*c; int row = vid >> 4; int d4 = (vid & 15)*4;
        float4 qv = *(const float4*)(qg + (size_t)(i0 + row)*DHD + d4);
        QT[(d4+0)*68 + row] = qv.x; QT[(d4+1)*68 + row] = qv.y;
        QT[(d4+2)*68 + row] = qv.z; QT[(d4+3)*68 + row] = qv.w;
    }

    float o[4][4] = {};
    float mrow[4] = {-1e30f, -1e30f, -1e30f, -1e30f};
    float lrow[4] = {};
    int nkt = (i0 >> 6) + 1;

    for (int kt = 0; kt < nkt; kt++) {
        int j0 = kt * 64;
        __syncthreads();   // protect previous P^T/V use before reload
        #pragma unroll
        for (int c = 0; c < 4; c++) {
            int vid = t + 256*c; int row = vid >> 4; int d4 = (vid & 15)*4;
            float4 kv = *(const float4*)(kg + (size_t)(j0 + row)*DHD + d4);
            KT[(d4+0)*68 + row] = kv.x; KT[(d4+1)*68 + row] = kv.y;
            KT[(d4+2)*68 + row] = kv.z; KT[(d4+3)*68 + row] = kv.w;
            *(float4*)(VS + row*68 + d4) = *(const float4*)(vg + (size_t)(j0 + row)*DHD + d4);
        }
        int base = (SS - 1) + j0 - i0 - 63;   // always >= 0
        #pragma unroll
        for (int c = 0; c < 8; c++) {
            int vid = t + 256*c; int u = vid >> 4; int d4 = (vid & 15)*4;
            int m = base + u;
            float4 ev = (m < SS) ? *(const float4*)(E + (size_t)m*DHD + d4)
                                 : make_float4(0.f, 0.f, 0.f, 0.f);
            ET[(d4+0)*132 + u] = ev.x; ET[(d4+1)*132 + u] = ev.y;
            ET[(d4+2)*132 + u] = ev.z; ET[(d4+3)*132 + u] = ev.w;
        }
        if (t < 64) KP[t] = g_keypad[b*SS + j0 + t];
        __syncthreads();

        // GEMM1: qk tile + Z band tile
        float aqk[4][4] = {};
        float az[4][8]  = {};
        #pragma unroll 4
        for (int d = 0; d < 64; d++) {
            float4 qf = *(const float4*)(QT + d*68 + ty*4);
            float4 kf = *(const float4*)(KT + d*68 + tx*4);
            float4 e0 = *(const float4*)(ET + d*132 + tx*8);
            float4 e1 = *(const float4*)(ET + d*132 + tx*8 + 4);
            float qa[4] = {qf.x, qf.y, qf.z, qf.w};
            float ka[4] = {kf.x, kf.y, kf.z, kf.w};
            float ea[8] = {e0.x, e0.y, e0.z, e0.w, e1.x, e1.y, e1.z, e1.w};
            #pragma unroll
            for (int ii = 0; ii < 4; ii++) {
                #pragma unroll
                for (int jj = 0; jj < 4; jj++) aqk[ii][jj] += qa[ii]*ka[jj];
                #pragma unroll
                for (int uu = 0; uu < 8; uu++) az[ii][uu] += qa[ii]*ea[uu];
            }
        }
        __syncthreads();                 // everyone done reading ET, KT
        #pragma unroll
        for (int ii = 0; ii < 4; ii++)
            #pragma unroll
            for (int uu = 0; uu < 8; uu++)
                ET[(ty*4 + ii)*132 + tx*8 + uu] = az[ii][uu];   // Z[i][u]
        __syncthreads();

        // logits + online softmax; write P^T into KT region
        #pragma unroll
        for (int ii = 0; ii < 4; ii++) {
            int il = ty*4 + ii; int i = i0 + il;
            float lg[4];
            #pragma unroll
            for (int jj = 0; jj < 4; jj++) {
                int jl = tx*4 + jj; int j = j0 + jl;
                int u = jl - il + 63;
                bool valid = (j <= i) && (KP[jl] == 0);
                lg[jj] = valid ? (aqk[ii][jj] + ET[il*132 + u]) * 0.125f : -1e30f;
            }
            float tm = fmaxf(fmaxf(lg[0], lg[1]), fmaxf(lg[2], lg[3]));
            tm = fmaxf(tm, __shfl_xor_sync(0xffffffffu, tm, 1));
            tm = fmaxf(tm, __shfl_xor_sync(0xffffffffu, tm, 2));
            tm = fmaxf(tm, __shfl_xor_sync(0xffffffffu, tm, 4));
            tm = fmaxf(tm, __shfl_xor_sync(0xffffffffu, tm, 8));
            float mn = fmaxf(mrow[ii], tm);
            float corr = __expf(mrow[ii] - mn);
            float rs = 0.f;
            #pragma unroll
            for (int jj = 0; jj < 4; jj++) {
                float p = __expf(lg[jj] - mn);
                KT[(tx*4 + jj)*68 + il] = p;       // P^T[j][i]
                rs += p;
            }
            rs += __shfl_xor_sync(0xffffffffu, rs, 1);
            rs += __shfl_xor_sync(0xffffffffu, rs, 2);
            rs += __shfl_xor_sync(0xffffffffu, rs, 4);
            rs += __shfl_xor_sync(0xffffffffu, rs, 8);
            lrow[ii] = lrow[ii]*corr + rs;
            mrow[ii] = mn;
            #pragma unroll
            for (int dd = 0; dd < 4; dd++) o[ii][dd] *= corr;
        }
        __syncthreads();

        // GEMM2: O += P V
        #pragma unroll 4
        for (int j = 0; j < 64; j++) {
            float4 pf = *(const float4*)(KT + j*68 + ty*4);
            float4 vf = *(const float4*)(VS + j*68 + tx*4);
            float pa[4] = {pf.x, pf.y, pf.z, pf.w};
            float va[4] = {vf.x, vf.y, vf.z, vf.w};
            #pragma unroll
            for (int ii = 0; ii < 4; ii++)
                #pragma unroll
                for (int dd = 0; dd < 4; dd++)
                    o[ii][dd] += pa[ii]*va[dd];
        }
    }

    #pragma unroll
    for (int ii = 0; ii < 4; ii++) {
        int i = i0 + ty*4 + ii;
        float inv = 1.0f / lrow[ii];
        #pragma unroll
        for (int dd = 0; dd < 4; dd++)
            g_attn[((size_t)(b*SS + i))*DD + h*DHD + tx*4 + dd] = o[ii][dd]*inv;
    }
}

// ---------------- host orchestration -----------------------------------------
extern "C" void kernel_launch(void* const* d_in, const int* in_sizes, int n_in,
                              void* d_out, int out_size) {
    const int*   toks   = (const int*)  d_in[0];
    const float* cond   = (const float*)d_in[1];
    const float* ttc    = (const float*)d_in[2];
    const float* emb    = (const float*)d_in[3];
    const float* pos    = (const float*)d_in[4];
    const float* cW1    = (const float*)d_in[5];
    const float* cb1    = (const float*)d_in[6];
    const float* cW2    = (const float*)d_in[7];
    const float* cb2    = (const float*)d_in[8];
    const float* nullc  = (const float*)d_in[9];
    const float* ttcW   = (const float*)d_in[10];
    const float* ttcb   = (const float*)d_in[11];
    const float* Wq     = (const float*)d_in[12];
    const float* Wk     = (const float*)d_in[13];
    const float* Wv     = (const float*)d_in[14];
    const float* Wo     = (const float*)d_in[15];
    const float* bq     = (const float*)d_in[16];
    const float* bk     = (const float*)d_in[17];
    const float* bv     = (const float*)d_in[18];
    const float* bo     = (const float*)d_in[19];
    const float* E      = (const float*)d_in[20];
    const float* fW1    = (const float*)d_in[21];
    const float* fb1    = (const float*)d_in[22];
    const float* fW2    = (const float*)d_in[23];
    const float* fb2    = (const float*)d_in[24];
    const float* ln1g   = (const float*)d_in[25];
    const float* ln1b   = (const float*)d_in[26];
    const float* ln2g   = (const float*)d_in[27];
    const float* ln2b   = (const float*)d_in[28];
    const float* fcW    = (const float*)d_in[29];
    const float* fcb    = (const float*)d_in[30];
    float* out = (float*)d_out;

    float *px, *pq, *pk, *pv, *pattn, *pres, *pout1, *ph;
    cudaGetSymbolAddress((void**)&px,    g_x);
    cudaGetSymbolAddress((void**)&pq,    g_q);
    cudaGetSymbolAddress((void**)&pk,    g_k);
    cudaGetSymbolAddress((void**)&pv,    g_v);
    cudaGetSymbolAddress((void**)&pattn, g_attn);
    cudaGetSymbolAddress((void**)&pres,  g_res);
    cudaGetSymbolAddress((void**)&pout1, g_out1);
    cudaGetSymbolAddress((void**)&ph,    g_h);

    cudaFuncSetAttribute(k_attn, cudaFuncAttributeMaxDynamicSharedMemorySize, ATT_SMEM);

    k_misc<<<(BS + 255)/256, 256>>>(toks, ttc);
    k_build_x<<<BS, 128>>>(toks, cond, emb, pos, cW1, cb1, cW2, cb2, nullc);

    dim3 gP(DD/64, BS/64);      // (8, 64)
    dim3 gF1(DI/64, BS/64);     // (32, 64)
    dim3 gA(SS/64, HH, BB);     // (32, 8, 2)

    for (int l = 0; l < NL; l++) {
        gemm64<0><<<gP, 256>>>(px, Wq + (size_t)l*DD*DD, bq + l*DD, nullptr, pq, BS, DD, DD, nullptr, nullptr);
        gemm64<0><<<gP, 256>>>(px, Wk + (size_t)l*DD*DD, bk + l*DD, nullptr, pk, BS, DD, DD, nullptr, nullptr);
        gemm64<0><<<gP, 256>>>(px, Wv + (size_t)l*DD*DD, bv + l*DD, nullptr, pv, BS, DD, DD, nullptr, nullptr);
        k_attn<<<gA, 256, ATT_SMEM>>>(E + (size_t)l*SS*DHD);
        gemm64<1><<<gP, 256>>>(pattn, Wo + (size_t)l*DD*DD, bo + l*DD, px, pres, BS, DD, DD, nullptr, nullptr);
        k_ln<<<BS, 128>>>(pres, pout1, ln1g + l*DD, ln1b + l*DD);
        gemm64<2><<<gF1, 256>>>(pout1, fW1 + (size_t)l*DD*DI, fb1 + l*DI, nullptr, ph, BS, DI, DD, ttcW, ttcb);
        gemm64<1><<<gP, 256>>>(ph, fW2 + (size_t)l*DI*DD, fb2 + l*DD, pout1, pres, BS, DD, DI, nullptr, nullptr);
        k_ln<<<BS, 128>>>(pres, px, ln2g + l*DD, ln2b + l*DD);
    }
    gemm64<3><<<dim3(VV/64, BS/64), 256>>>(px, fcW, fcb, nullptr, out, BS, VV, DD, nullptr, nullptr);
}